// round 8
// baseline (speedup 1.0000x reference)
#include <cuda_runtime.h>
#include <cuda_fp16.h>

#define Bn 4
#define Sn 256
#define Hn 160
#define NHn 8
#define HDn 20
#define FFn 640
#define MAXLENn 512
#define TBLn 1025
#define BSn (Bn*Sn)
#define R2 8
#define TR 16
#define TBLOCKS 65     // ceil(1025/16)
#define RPAD 24        // uint4 per table row (20 data + 4 pad -> 384B, 128B aligned)
#define RPU 96         // row pitch in uint (4B) units = RPAD*4

// ------------------------- device scratch (static, no allocs) ----------------
__device__ uint4 dPT[4 * TBLn * RPAD];  // fused pe tables fp16, 384B padded rows
__device__ float dKT[Bn * Hn * Sn];     // K transposed: [b][hd][j]
__device__ float dV[BSn * Hn];
__device__ float dQU[BSn * Hn];         // q + u
__device__ float dG[BSn * NHn * Hn];    // g[b,i,h,c]
__device__ float dATT[BSn * Hn];
__device__ float dY1[BSn * Hn];
__device__ float dH1[BSn * FFn];

__device__ __forceinline__ void ffma2(unsigned long long& d, unsigned long long a,
                                      unsigned long long b) {
    asm("fma.rn.f32x2 %0, %1, %2, %3;" : "=l"(d) : "l"(a), "l"(b), "l"(d));
}
__device__ __forceinline__ __half2 u2h(unsigned x) {
    return *reinterpret_cast<__half2*>(&x);
}
__device__ __forceinline__ unsigned long long packf2(float2 f) {
    unsigned long long r;
    asm("mov.b64 %0, {%1,%2};" : "=l"(r) : "f"(f.x), "f"(f.y));
    return r;
}
__device__ __forceinline__ float2 unpackf2(unsigned long long v) {
    float2 f;
    asm("mov.b64 {%0,%1}, %2;" : "=f"(f.x), "=f"(f.y) : "l"(v));
    return f;
}
__device__ __forceinline__ unsigned sum4relu(unsigned a, unsigned b, unsigned c,
                                             unsigned d, __half2 hz) {
    __half2 s = __hmax2(__hadd2(__hadd2(u2h(a), u2h(b)), __hadd2(u2h(c), u2h(d))), hz);
    return *reinterpret_cast<unsigned*>(&s);
}

// ------------------------- K1: P_t = pe_t @ W_fus[t] (+b_fus for t=0), fp16 out
__global__ void k_tables(const float* __restrict__ pe_a, const float* __restrict__ pe_b,
                         const float* __restrict__ W_fus, const float* __restrict__ b_fus,
                         int t0) {
    int sel = blockIdx.x / TBLOCKS;
    int t = t0 + sel;
    int r0 = (blockIdx.x % TBLOCKS) * TR;
    const float* pe = sel ? pe_b : pe_a;
    __shared__ float rows[TR][Hn];
    int c = threadIdx.x;
#pragma unroll
    for (int r = 0; r < TR; r++) {
        int rr = r0 + r;
        rows[r][c] = (rr < TBLn) ? pe[rr * Hn + c] : 0.f;
    }
    __syncthreads();
    float bias = (t == 0) ? b_fus[c] : 0.f;
    float acc[TR];
#pragma unroll
    for (int r = 0; r < TR; r++) acc[r] = bias;
    const float* wf = W_fus + t * Hn * Hn + c;
    for (int k0 = 0; k0 < Hn; k0 += 8) {
        float wb[8];
#pragma unroll
        for (int q = 0; q < 8; q++) wb[q] = wf[(k0 + q) * Hn];
#pragma unroll
        for (int q = 0; q < 8; q++)
#pragma unroll
            for (int r = 0; r < TR; r++) acc[r] += rows[r][k0 + q] * wb[q];
    }
    __half* out = (__half*)dPT;
#pragma unroll
    for (int r = 0; r < TR; r++) {
        int rr = r0 + r;
        if (rr < TBLn) {
            size_t rowb = (size_t)(t * TBLn + rr) * (RPAD * 8);
            out[rowb + c] = __float2half(acc[r]);
            if (c < 32) out[rowb + Hn + c] = __half(0.f);  // zero the pad
        }
    }
}

// ------------------------- K2: q/k/v projections + g ------------------------
__global__ void k_qkvg(const float* __restrict__ inp,
                       const float* __restrict__ Wq, const float* __restrict__ bq,
                       const float* __restrict__ Wk, const float* __restrict__ bk,
                       const float* __restrict__ Wv, const float* __restrict__ bv,
                       const float* __restrict__ Wr,
                       const float* __restrict__ u, const float* __restrict__ v) {
    int row0 = blockIdx.x * R2;
    int b = row0 >> 8;
    int i0 = row0 & 255;
    int c = threadIdx.x;
    __shared__ float xs[R2][Hn];
    __shared__ float qv[R2][Hn];
#pragma unroll
    for (int r = 0; r < R2; r++) xs[r][c] = inp[(row0 + r) * Hn + c];
    __syncthreads();

    float acc[R2];
    // ---- Q (batched loads, MLP=8)
#pragma unroll
    for (int r = 0; r < R2; r++) acc[r] = bq[c];
    {
        const float* wp = Wq + c;
        for (int k0 = 0; k0 < Hn; k0 += 8) {
            float wb[8];
#pragma unroll
            for (int q = 0; q < 8; q++) wb[q] = wp[(k0 + q) * Hn];
#pragma unroll
            for (int q = 0; q < 8; q++)
#pragma unroll
                for (int r = 0; r < R2; r++) acc[r] += xs[r][k0 + q] * wb[q];
        }
    }
    {
        float uu = u[c], vv = v[c];
#pragma unroll
        for (int r = 0; r < R2; r++) {
            dQU[(row0 + r) * Hn + c] = acc[r] + uu;
            qv[r][c] = acc[r] + vv;
        }
    }
    // ---- K -> transposed store
#pragma unroll
    for (int r = 0; r < R2; r++) acc[r] = bk[c];
    {
        const float* wp = Wk + c;
        for (int k0 = 0; k0 < Hn; k0 += 8) {
            float wb[8];
#pragma unroll
            for (int q = 0; q < 8; q++) wb[q] = wp[(k0 + q) * Hn];
#pragma unroll
            for (int q = 0; q < 8; q++)
#pragma unroll
                for (int r = 0; r < R2; r++) acc[r] += xs[r][k0 + q] * wb[q];
        }
    }
#pragma unroll
    for (int r = 0; r < R2; r++) dKT[((size_t)b * Hn + c) * Sn + (i0 + r)] = acc[r];
    // ---- V
#pragma unroll
    for (int r = 0; r < R2; r++) acc[r] = bv[c];
    {
        const float* wp = Wv + c;
        for (int k0 = 0; k0 < Hn; k0 += 8) {
            float wb[8];
#pragma unroll
            for (int q = 0; q < 8; q++) wb[q] = wp[(k0 + q) * Hn];
#pragma unroll
            for (int q = 0; q < 8; q++)
#pragma unroll
                for (int r = 0; r < R2; r++) acc[r] += xs[r][k0 + q] * wb[q];
        }
    }
#pragma unroll
    for (int r = 0; r < R2; r++) dV[(row0 + r) * Hn + c] = acc[r];
    __syncthreads();

    // ---- g: row c of Wr is contiguous; float4 loads give MLP
    const float4* wr4 = reinterpret_cast<const float4*>(Wr + (size_t)c * Hn);
    for (int h = 0; h < NHn; h++) {
        float a2[R2];
#pragma unroll
        for (int r = 0; r < R2; r++) a2[r] = 0.f;
        float4 wv4[5];
#pragma unroll
        for (int d4 = 0; d4 < 5; d4++) wv4[d4] = wr4[h * 5 + d4];
#pragma unroll
        for (int d4 = 0; d4 < 5; d4++) {
            int hd = h * HDn + d4 * 4;
#pragma unroll
            for (int r = 0; r < R2; r++) {
                a2[r] += qv[r][hd + 0] * wv4[d4].x + qv[r][hd + 1] * wv4[d4].y +
                         qv[r][hd + 2] * wv4[d4].z + qv[r][hd + 3] * wv4[d4].w;
            }
        }
#pragma unroll
        for (int r = 0; r < R2; r++) dG[((size_t)(row0 + r) * NHn + h) * Hn + c] = a2[r];
    }
}

// ------------------------- K3: fused A_C + B_D(warp-per-j) + softmax + attn@V
__global__ void __launch_bounds__(256, 2) k_attn(const int* __restrict__ pos_s,
                                                 const int* __restrict__ pos_e,
                                                 const int* __restrict__ seq_len,
                                                 const int* __restrict__ lex) {
    int b = blockIdx.x >> 8;
    int i = blockIdx.x & 255;
    int tid = threadIdx.x;
    int lane = tid & 31;
    int w = tid >> 5;

    __shared__ float sc[NHn][257];
    __shared__ int pssO[Sn], pesO[Sn];    // pos * RPU (uint units)
    __shared__ float quv[Hn];
    __shared__ float rinv[NHn];
    __shared__ int psi_s, pei_s, lim_s;

    {
        int ps = pos_s[b * Sn + tid];
        int pe = pos_e[b * Sn + tid];
        pssO[tid] = ps * RPU;
        pesO[tid] = pe * RPU;
        if (tid == i) { psi_s = ps; pei_s = pe; }
        if (tid == 0) lim_s = seq_len[b] + lex[0];
    }
    if (tid < Hn) quv[tid] = dQU[(size_t)(b * Sn + i) * Hn + tid];

    // ---- g into registers: lane owns channel pairs (2l,2l+1), (+64), (+128)
    unsigned long long greg[NHn][3];
    {
        const float* gp = dG + (size_t)(b * Sn + i) * NHn * Hn + 2 * lane;
        bool has2 = (2 * lane + 128) < Hn;  // lane < 16
#pragma unroll
        for (int h = 0; h < NHn; h++) {
            greg[h][0] = *reinterpret_cast<const unsigned long long*>(gp + h * Hn);
            greg[h][1] = *reinterpret_cast<const unsigned long long*>(gp + h * Hn + 64);
            greg[h][2] = has2 ? *reinterpret_cast<const unsigned long long*>(gp + h * Hn + 128)
                              : 0ull;
        }
    }
    __syncthreads();

    int lim = lim_s;

    // ---- Phase AC (unscaled); invalid j get -1e15
    if (tid < lim) {
        float acc[NHn];
#pragma unroll
        for (int h = 0; h < NHn; h++) acc[h] = 0.f;
#pragma unroll
        for (int h = 0; h < NHn; h++) {
            const float* kp = dKT + ((size_t)b * Hn + h * HDn) * Sn + tid;
#pragma unroll
            for (int d = 0; d < HDn; d++) acc[h] += quv[h * HDn + d] * kp[(size_t)d * Sn];
        }
#pragma unroll
        for (int h = 0; h < NHn; h++) sc[h][tid] = acc[h];
    } else {
#pragma unroll
        for (int h = 0; h < NHn; h++) sc[h][tid] = -1e15f;
    }
    __syncthreads();

    // ---- Phase BD: warp w owns j in [w*32, w*32+32); whole warp per j
    {
        const unsigned* B0 = (const unsigned*)dPT + (size_t)(0 * TBLn + psi_s + MAXLENn) * RPU + lane;
        const unsigned* B1 = (const unsigned*)dPT + (size_t)(1 * TBLn + psi_s + MAXLENn) * RPU + lane;
        const unsigned* B2 = (const unsigned*)dPT + (size_t)(2 * TBLn + pei_s + MAXLENn) * RPU + lane;
        const unsigned* B3 = (const unsigned*)dPT + (size_t)(3 * TBLn + pei_s + MAXLENn) * RPU + lane;
        const __half2 hz = __float2half2_rn(0.f);

#pragma unroll 1
        for (int it = 0; it < 32; it++) {
            int j = (w << 5) + it;
            if (j >= lim) break;                 // uniform within warp
            int oS = pssO[j], oE = pesO[j];
            const unsigned* q0 = B0 - oS;
            const unsigned* q1 = B1 - oE;
            const unsigned* q2 = B2 - oS;
            const unsigned* q3 = B3 - oE;
            unsigned s0 = sum4relu(q0[0],  q1[0],  q2[0],  q3[0],  hz);
            unsigned s1 = sum4relu(q0[32], q1[32], q2[32], q3[32], hz);
            unsigned s2 = sum4relu(q0[64], q1[64], q2[64], q3[64], hz);
            unsigned long long r0 = packf2(__half22float2(u2h(s0)));
            unsigned long long r1 = packf2(__half22float2(u2h(s1)));
            unsigned long long r2 = packf2(__half22float2(u2h(s2)));

            float a[NHn];
#pragma unroll
            for (int h = 0; h < NHn; h++) {
                unsigned long long acc2 = 0ull;
                ffma2(acc2, r0, greg[h][0]);
                ffma2(acc2, r1, greg[h][1]);
                ffma2(acc2, r2, greg[h][2]);
                float2 f = unpackf2(acc2);
                a[h] = f.x + f.y;
            }
            // reduce-scatter over 32 lanes: lane l ends owning head l>>2
            {
                bool hb = lane & 16;
#pragma unroll
                for (int k2 = 0; k2 < 4; k2++) {
                    float send = hb ? a[k2] : a[k2 + 4];
                    float got = __shfl_xor_sync(0xffffffffu, send, 16);
                    a[k2] = (hb ? a[k2 + 4] : a[k2]) + got;
                }
            }
            {
                bool hb = lane & 8;
#pragma unroll
                for (int k2 = 0; k2 < 2; k2++) {
                    float send = hb ? a[k2] : a[k2 + 2];
                    float got = __shfl_xor_sync(0xffffffffu, send, 8);
                    a[k2] = (hb ? a[k2 + 2] : a[k2]) + got;
                }
            }
            {
                bool hb = lane & 4;
                float send = hb ? a[0] : a[1];
                float got = __shfl_xor_sync(0xffffffffu, send, 4);
                a[0] = (hb ? a[1] : a[0]) + got;
            }
            a[0] += __shfl_xor_sync(0xffffffffu, a[0], 2);
            a[0] += __shfl_xor_sync(0xffffffffu, a[0], 1);
            if ((lane & 3) == 0) sc[lane >> 2][j] += a[0];
        }
    }
    __syncthreads();

    // ---- scale + mask
    {
        bool valid = tid < lim;
        const float scale = 0.223606797749979f;  // 1/sqrt(20)
#pragma unroll
        for (int h = 0; h < NHn; h++) {
            float sv = sc[h][tid] * scale;
            sc[h][tid] = valid ? sv : -1e15f;
        }
    }
    __syncthreads();

    // ---- per-head softmax (warp w = head w); unnormalized p + 1/sum
    {
        int h = w;
        float m = -1e30f;
#pragma unroll
        for (int q = 0; q < 8; q++) m = fmaxf(m, sc[h][lane + q * 32]);
#pragma unroll
        for (int off = 16; off; off >>= 1) m = fmaxf(m, __shfl_xor_sync(0xffffffffu, m, off));
        float ssum = 0.f;
#pragma unroll
        for (int q = 0; q < 8; q++) {
            float p = __expf(sc[h][lane + q * 32] - m);
            sc[h][lane + q * 32] = p;
            ssum += p;
        }
#pragma unroll
        for (int off = 16; off; off >>= 1) ssum += __shfl_xor_sync(0xffffffffu, ssum, off);
        if (lane == 0) rinv[h] = 1.0f / ssum;
    }
    __syncthreads();

    // ---- out[c] = (sum_j p[h][j] * V[b,j,c]) * rinv[h]
    if (tid < Hn) {
        int c = tid;
        int h = c / HDn;
        const float* vp = dV + (size_t)b * Sn * Hn + c;
        float acc = 0.f;
#pragma unroll 8
        for (int j = 0; j < Sn; j++) acc += sc[h][j] * vp[(size_t)j * Hn];
        dATT[((size_t)b * Sn + i) * Hn + c] = acc * rinv[h];
    }
}

// ------------------------- K4: @W_fin + b_fin, x2, LN1 (R2=8, batched) ------
__global__ void k_fin_ln(const float* __restrict__ W_fin, const float* __restrict__ b_fin,
                         const float* __restrict__ g1, const float* __restrict__ be1) {
    int row0 = blockIdx.x * R2;
    int c = threadIdx.x;
    int lane = c & 31, w = c >> 5;
    __shared__ float xs[R2][Hn];
    __shared__ float ys[R2][Hn];
    __shared__ float part1[5], part2[5];
    __shared__ float mu_s, rs_s;
#pragma unroll
    for (int r = 0; r < R2; r++) xs[r][c] = dATT[(row0 + r) * Hn + c];
    __syncthreads();
    float acc[R2];
#pragma unroll
    for (int r = 0; r < R2; r++) acc[r] = b_fin[c];
    {
        const float* wp = W_fin + c;
        for (int k0 = 0; k0 < Hn; k0 += 8) {
            float wb[8];
#pragma unroll
            for (int q = 0; q < 8; q++) wb[q] = wp[(k0 + q) * Hn];
#pragma unroll
            for (int q = 0; q < 8; q++)
#pragma unroll
                for (int r = 0; r < R2; r++) acc[r] += xs[r][k0 + q] * wb[q];
        }
    }
#pragma unroll
    for (int r = 0; r < R2; r++) ys[r][c] = 2.f * acc[r];
    __syncthreads();
    for (int r = 0; r < R2; r++) {
        float v = ys[r][c];
        float s1 = v, s2 = v * v;
#pragma unroll
        for (int off = 16; off; off >>= 1) {
            s1 += __shfl_xor_sync(0xffffffffu, s1, off);
            s2 += __shfl_xor_sync(0xffffffffu, s2, off);
        }
        if (lane == 0) { part1[w] = s1; part2[w] = s2; }
        __syncthreads();
        if (c == 0) {
            float a = 0.f, q = 0.f;
#pragma unroll
            for (int t = 0; t < 5; t++) { a += part1[t]; q += part2[t]; }
            float mu = a / Hn;
            mu_s = mu;
            rs_s = rsqrtf(q / Hn - mu * mu + 1e-5f);
        }
        __syncthreads();
        dY1[(row0 + r) * Hn + c] = (v - mu_s) * rs_s * g1[c] + be1[c];
        __syncthreads();
    }
}

// ------------------------- K5: FFN1 = relu(y1 @ W1 + b1), 16-row x col-half --
#define RF1 16
__global__ void k_ffn1(const float* __restrict__ W1, const float* __restrict__ b1) {
    int rb = blockIdx.x >> 1;
    int half = blockIdx.x & 1;
    int row0 = rb * RF1;
    int t = threadIdx.x;  // 320
    int c = half * 320 + t;
    __shared__ float xs[RF1 * Hn];
    for (int q = t; q < RF1 * Hn; q += 320) xs[q] = dY1[row0 * Hn + q];
    __syncthreads();
    float a0[RF1];
#pragma unroll
    for (int r = 0; r < RF1; r++) a0[r] = b1[c];
    {
        const float* wp = W1 + c;
        for (int k0 = 0; k0 < Hn; k0 += 8) {
            float wb[8];
#pragma unroll
            for (int q = 0; q < 8; q++) wb[q] = wp[(k0 + q) * FFn];
#pragma unroll
            for (int q = 0; q < 8; q++)
#pragma unroll
                for (int r = 0; r < RF1; r++) a0[r] += xs[r * Hn + k0 + q] * wb[q];
        }
    }
#pragma unroll
    for (int r = 0; r < RF1; r++) dH1[(row0 + r) * FFn + c] = fmaxf(a0[r], 0.f);
}

// ------------------------- K6: FFN2 + b2, x2, LN2 -> out (split-k x2) -------
__global__ void k_ffn2_ln(const float* __restrict__ W2, const float* __restrict__ b2,
                          const float* __restrict__ g2, const float* __restrict__ be2,
                          float* __restrict__ out) {
    int row0 = blockIdx.x * R2;
    int tid = threadIdx.x;  // 320
    int kh = (tid >= Hn) ? 1 : 0;
    int c = tid - kh * Hn;
    int lane = tid & 31, w = tid >> 5;
    __shared__ float hs[R2 * FFn];
    __shared__ float psum[R2][Hn];
    __shared__ float ys[R2][Hn];
    __shared__ float part1[5], part2[5];
    __shared__ float mu_s, rs_s;
    for (int q = tid; q < R2 * FFn; q += 320) hs[q] = dH1[row0 * FFn + q];
    __syncthreads();
    float acc[R2];
#pragma unroll
    for (int r = 0; r < R2; r++) acc[r] = kh ? 0.f : b2[c];
    int kbase = kh * 320;
    {
        const float* wp = W2 + (size_t)kbase * Hn + c;
        for (int k0 = 0; k0 < 320; k0 += 8) {
            float wb[8];
#pragma unroll
            for (int q = 0; q < 8; q++) wb[q] = wp[(k0 + q) * Hn];
#pragma unroll
            for (int q = 0; q < 8; q++)
#pragma unroll
                for (int r = 0; r < R2; r++) acc[r] += hs[r * FFn + kbase + k0 + q] * wb[q];
        }
    }
    if (kh) {
#pragma unroll
        for (int r = 0; r < R2; r++) psum[r][c] = acc[r];
    }
    __syncthreads();
    if (!kh) {
#pragma unroll
        for (int r = 0; r < R2; r++) ys[r][c] = 2.f * (acc[r] + psum[r][c]);
    }
    __syncthreads();
    for (int r = 0; r < R2; r++) {
        float v = (tid < Hn) ? ys[r][c] : 0.f;
        float s1 = v, s2 = v * v;
#pragma unroll
        for (int off = 16; off; off >>= 1) {
            s1 += __shfl_xor_sync(0xffffffffu, s1, off);
            s2 += __shfl_xor_sync(0xffffffffu, s2, off);
        }
        if (lane == 0 && w < 5) { part1[w] = s1; part2[w] = s2; }
        __syncthreads();
        if (tid == 0) {
            float a = 0.f, q = 0.f;
#pragma unroll
            for (int t = 0; t < 5; t++) { a += part1[t]; q += part2[t]; }
            float mu = a / Hn;
            mu_s = mu;
            rs_s = rsqrtf(q / Hn - mu * mu + 1e-5f);
        }
        __syncthreads();
        if (tid < Hn) out[(row0 + r) * Hn + c] = (ys[r][c] - mu_s) * rs_s * g2[c] + be2[c];
        __syncthreads();
    }
}

// ------------------------- launch -------------------------------------------
extern "C" void kernel_launch(void* const* d_in, const int* in_sizes, int n_in,
                              void* d_out, int out_size) {
    const float* inp   = (const float*)d_in[0];
    const int* pos_s   = (const int*)d_in[1];
    const int* pos_e   = (const int*)d_in[2];
    const int* seq_len = (const int*)d_in[3];
    const int* lex     = (const int*)d_in[4];
    const float* pe_ss = (const float*)d_in[5];
    const float* pe_se = (const float*)d_in[6];
    const float* pe_es = (const float*)d_in[7];
    const float* pe_ee = (const float*)d_in[8];
    const float* W_fus = (const float*)d_in[9];
    const float* b_fus = (const float*)d_in[10];
    const float* Wq    = (const float*)d_in[11];
    const float* bq    = (const float*)d_in[12];
    const float* Wk    = (const float*)d_in[13];
    const float* bk    = (const float*)d_in[14];
    const float* Wv    = (const float*)d_in[15];
    const float* bv    = (const float*)d_in[16];
    const float* Wr    = (const float*)d_in[17];
    // d_in[18] = br: constant over j inside softmax -> cancels exactly, unused
    const float* u     = (const float*)d_in[19];
    const float* v     = (const float*)d_in[20];
    const float* W_fin = (const float*)d_in[21];
    const float* b_fin = (const float*)d_in[22];
    const float* ln1_g = (const float*)d_in[23];
    const float* ln1_b = (const float*)d_in[24];
    const float* W1    = (const float*)d_in[25];
    const float* b1    = (const float*)d_in[26];
    const float* W2    = (const float*)d_in[27];
    const float* b2    = (const float*)d_in[28];
    const float* ln2_g = (const float*)d_in[29];
    const float* ln2_b = (const float*)d_in[30];

    k_tables<<<2 * TBLOCKS, Hn>>>(pe_ss, pe_se, W_fus, b_fus, 0);     // 1
    k_tables<<<2 * TBLOCKS, Hn>>>(pe_es, pe_ee, W_fus, b_fus, 2);     // 2
    k_qkvg<<<BSn / R2, Hn>>>(inp, Wq, bq, Wk, bk, Wv, bv, Wr, u, v);  // 3
    k_attn<<<BSn, 256>>>(pos_s, pos_e, seq_len, lex);                 // 4 (profiled)
    k_fin_ln<<<BSn / R2, Hn>>>(W_fin, b_fin, ln1_g, ln1_b);           // 5
    k_ffn1<<<(BSn / RF1) * 2, 320>>>(W1, b1);                         // 6
    k_ffn2_ln<<<BSn / R2, 320>>>(W2, b2, ln2_g, ln2_b, (float*)d_out);// 7
}

// round 9
// speedup vs baseline: 1.2553x; 1.2553x over previous
#include <cuda_runtime.h>
#include <cuda_fp16.h>

#define Bn 4
#define Sn 256
#define Hn 160
#define NHn 8
#define HDn 20
#define FFn 640
#define MAXLENn 512
#define TBLn 1025
#define BSn (Bn*Sn)
#define R2 8
#define TR 16
#define TBLOCKS 65     // ceil(1025/16)
#define RPAD 24        // uint4 per table row (20 data + 4 pad -> 384B, 128B aligned)
#define RPU 96         // row pitch in uint (4B) units = RPAD*4

// ------------------------- device scratch (static, no allocs) ----------------
__device__ uint4 dPT[4 * TBLn * RPAD];  // fused pe tables fp16, 384B padded rows
__device__ float dKT[Bn * Hn * Sn];     // K transposed: [b][hd][j]
__device__ float dV[BSn * Hn];
__device__ float dQU[BSn * Hn];         // q + u
__device__ float dG[BSn * NHn * Hn];    // g[b,i,h,c]
__device__ float dATT[BSn * Hn];
__device__ float dY1[BSn * Hn];
__device__ float dH1[BSn * FFn];

__device__ __forceinline__ __half2 u2h(unsigned x) {
    return *reinterpret_cast<__half2*>(&x);
}
__device__ __forceinline__ unsigned h2u(__half2 h) {
    return *reinterpret_cast<unsigned*>(&h);
}
__device__ __forceinline__ __half2 sum4relu_h(unsigned a, unsigned b, unsigned c,
                                              unsigned d, __half2 hz) {
    return __hmax2(__hadd2(__hadd2(u2h(a), u2h(b)), __hadd2(u2h(c), u2h(d))), hz);
}

// ------------------------- K1: P_t = pe_t @ W_fus[t] (+b_fus for t=0), fp16 out
__global__ void k_tables(const float* __restrict__ pe_a, const float* __restrict__ pe_b,
                         const float* __restrict__ W_fus, const float* __restrict__ b_fus,
                         int t0) {
    int sel = blockIdx.x / TBLOCKS;
    int t = t0 + sel;
    int r0 = (blockIdx.x % TBLOCKS) * TR;
    const float* pe = sel ? pe_b : pe_a;
    __shared__ float rows[TR][Hn];
    int c = threadIdx.x;
#pragma unroll
    for (int r = 0; r < TR; r++) {
        int rr = r0 + r;
        rows[r][c] = (rr < TBLn) ? pe[rr * Hn + c] : 0.f;
    }
    __syncthreads();
    float bias = (t == 0) ? b_fus[c] : 0.f;
    float acc[TR];
#pragma unroll
    for (int r = 0; r < TR; r++) acc[r] = bias;
    const float* wf = W_fus + t * Hn * Hn + c;
    for (int k0 = 0; k0 < Hn; k0 += 16) {
        float wb[16];
#pragma unroll
        for (int q = 0; q < 16; q++) wb[q] = wf[(k0 + q) * Hn];
#pragma unroll
        for (int q = 0; q < 16; q++)
#pragma unroll
            for (int r = 0; r < TR; r++) acc[r] += rows[r][k0 + q] * wb[q];
    }
    __half* out = (__half*)dPT;
#pragma unroll
    for (int r = 0; r < TR; r++) {
        int rr = r0 + r;
        if (rr < TBLn) {
            size_t rowb = (size_t)(t * TBLn + rr) * (RPAD * 8);
            out[rowb + c] = __float2half(acc[r]);
            if (c < 32) out[rowb + Hn + c] = __half(0.f);  // zero the pad
        }
    }
}

// ------------------------- K2: q/k/v projections + g ------------------------
__global__ void k_qkvg(const float* __restrict__ inp,
                       const float* __restrict__ Wq, const float* __restrict__ bq,
                       const float* __restrict__ Wk, const float* __restrict__ bk,
                       const float* __restrict__ Wv, const float* __restrict__ bv,
                       const float* __restrict__ Wr,
                       const float* __restrict__ u, const float* __restrict__ v) {
    int row0 = blockIdx.x * R2;
    int b = row0 >> 8;
    int i0 = row0 & 255;
    int c = threadIdx.x;
    __shared__ float xs[R2][Hn];
    __shared__ float qv[R2][Hn];
#pragma unroll
    for (int r = 0; r < R2; r++) xs[r][c] = inp[(row0 + r) * Hn + c];
    __syncthreads();

    float acc[R2];
    // ---- Q (batched loads, MLP=16)
#pragma unroll
    for (int r = 0; r < R2; r++) acc[r] = bq[c];
    {
        const float* wp = Wq + c;
        for (int k0 = 0; k0 < Hn; k0 += 16) {
            float wb[16];
#pragma unroll
            for (int q = 0; q < 16; q++) wb[q] = wp[(k0 + q) * Hn];
#pragma unroll
            for (int q = 0; q < 16; q++)
#pragma unroll
                for (int r = 0; r < R2; r++) acc[r] += xs[r][k0 + q] * wb[q];
        }
    }
    {
        float uu = u[c], vv = v[c];
#pragma unroll
        for (int r = 0; r < R2; r++) {
            dQU[(row0 + r) * Hn + c] = acc[r] + uu;
            qv[r][c] = acc[r] + vv;
        }
    }
    // ---- K -> transposed store
#pragma unroll
    for (int r = 0; r < R2; r++) acc[r] = bk[c];
    {
        const float* wp = Wk + c;
        for (int k0 = 0; k0 < Hn; k0 += 16) {
            float wb[16];
#pragma unroll
            for (int q = 0; q < 16; q++) wb[q] = wp[(k0 + q) * Hn];
#pragma unroll
            for (int q = 0; q < 16; q++)
#pragma unroll
                for (int r = 0; r < R2; r++) acc[r] += xs[r][k0 + q] * wb[q];
        }
    }
#pragma unroll
    for (int r = 0; r < R2; r++) dKT[((size_t)b * Hn + c) * Sn + (i0 + r)] = acc[r];
    // ---- V
#pragma unroll
    for (int r = 0; r < R2; r++) acc[r] = bv[c];
    {
        const float* wp = Wv + c;
        for (int k0 = 0; k0 < Hn; k0 += 16) {
            float wb[16];
#pragma unroll
            for (int q = 0; q < 16; q++) wb[q] = wp[(k0 + q) * Hn];
#pragma unroll
            for (int q = 0; q < 16; q++)
#pragma unroll
                for (int r = 0; r < R2; r++) acc[r] += xs[r][k0 + q] * wb[q];
        }
    }
#pragma unroll
    for (int r = 0; r < R2; r++) dV[(row0 + r) * Hn + c] = acc[r];
    __syncthreads();

    // ---- g: row c of Wr is contiguous; float4 loads give MLP
    const float4* wr4 = reinterpret_cast<const float4*>(Wr + (size_t)c * Hn);
    for (int h = 0; h < NHn; h++) {
        float a2[R2];
#pragma unroll
        for (int r = 0; r < R2; r++) a2[r] = 0.f;
        float4 wv4[5];
#pragma unroll
        for (int d4 = 0; d4 < 5; d4++) wv4[d4] = wr4[h * 5 + d4];
#pragma unroll
        for (int d4 = 0; d4 < 5; d4++) {
            int hd = h * HDn + d4 * 4;
#pragma unroll
            for (int r = 0; r < R2; r++) {
                a2[r] += qv[r][hd + 0] * wv4[d4].x + qv[r][hd + 1] * wv4[d4].y +
                         qv[r][hd + 2] * wv4[d4].z + qv[r][hd + 3] * wv4[d4].w;
            }
        }
#pragma unroll
        for (int r = 0; r < R2; r++) dG[((size_t)(row0 + r) * NHn + h) * Hn + c] = a2[r];
    }
}

// ------------------------- K3: fused A_C + B_D(warp-per-j) + softmax + attn@V
__global__ void __launch_bounds__(256, 3) k_attn(const int* __restrict__ pos_s,
                                                 const int* __restrict__ pos_e,
                                                 const int* __restrict__ seq_len,
                                                 const int* __restrict__ lex) {
    int b = blockIdx.x >> 8;
    int i = blockIdx.x & 255;
    int tid = threadIdx.x;
    int lane = tid & 31;
    int w = tid >> 5;

    __shared__ float sc[NHn][257];
    __shared__ int pssO[Sn], pesO[Sn];    // pos * RPU (uint units)
    __shared__ float quv[Hn];
    __shared__ float rinv[NHn];
    __shared__ int psi_s, pei_s, lim_s;

    {
        int ps = pos_s[b * Sn + tid];
        int pe = pos_e[b * Sn + tid];
        pssO[tid] = ps * RPU;
        pesO[tid] = pe * RPU;
        if (tid == i) { psi_s = ps; pei_s = pe; }
        if (tid == 0) lim_s = seq_len[b] + lex[0];
    }
    if (tid < Hn) quv[tid] = dQU[(size_t)(b * Sn + i) * Hn + tid];

    // ---- g into registers as fp16 half2: lane owns pairs (2l,2l+1),(+64),(+128)
    unsigned greg[NHn][3];
    {
        const float* gp = dG + (size_t)(b * Sn + i) * NHn * Hn + 2 * lane;
        bool has2 = lane < 16;
#pragma unroll
        for (int h = 0; h < NHn; h++) {
            float2 f0 = *reinterpret_cast<const float2*>(gp + h * Hn);
            float2 f1 = *reinterpret_cast<const float2*>(gp + h * Hn + 64);
            greg[h][0] = h2u(__float22half2_rn(f0));
            greg[h][1] = h2u(__float22half2_rn(f1));
            if (has2) {
                float2 f2 = *reinterpret_cast<const float2*>(gp + h * Hn + 128);
                greg[h][2] = h2u(__float22half2_rn(f2));
            } else {
                greg[h][2] = 0u;
            }
        }
    }
    __syncthreads();

    int lim = lim_s;

    // ---- Phase AC (unscaled); invalid j get -1e15
    if (tid < lim) {
        float acc[NHn];
#pragma unroll
        for (int h = 0; h < NHn; h++) acc[h] = 0.f;
#pragma unroll
        for (int h = 0; h < NHn; h++) {
            const float* kp = dKT + ((size_t)b * Hn + h * HDn) * Sn + tid;
#pragma unroll
            for (int d = 0; d < HDn; d++) acc[h] += quv[h * HDn + d] * kp[(size_t)d * Sn];
        }
#pragma unroll
        for (int h = 0; h < NHn; h++) sc[h][tid] = acc[h];
    } else {
#pragma unroll
        for (int h = 0; h < NHn; h++) sc[h][tid] = -1e15f;
    }
    __syncthreads();

    // ---- Phase BD: warp w owns j in [w*32, w*32+32); whole warp per j
    {
        const unsigned* PT = (const unsigned*)dPT;
        int C0 = (0 * TBLn + psi_s + MAXLENn) * RPU + lane;
        int C1 = (1 * TBLn + psi_s + MAXLENn) * RPU + lane;
        int C2 = (2 * TBLn + pei_s + MAXLENn) * RPU + lane;
        int C3 = (3 * TBLn + pei_s + MAXLENn) * RPU + lane;
        const __half2 hz = __float2half2_rn(0.f);

        int jbase = w << 5;
        int jmax = lim - jbase;
        if (jmax > 32) jmax = 32;
#pragma unroll 2
        for (int it = 0; it < jmax; it++) {
            int j = jbase + it;
            int oS = pssO[j], oE = pesO[j];
            int i0 = C0 - oS, i1 = C1 - oE, i2 = C2 - oS, i3 = C3 - oE;
            __half2 r0 = sum4relu_h(PT[i0],      PT[i1],      PT[i2],      PT[i3],      hz);
            __half2 r1 = sum4relu_h(PT[i0 + 32], PT[i1 + 32], PT[i2 + 32], PT[i3 + 32], hz);
            __half2 r2 = sum4relu_h(PT[i0 + 64], PT[i1 + 64], PT[i2 + 64], PT[i3 + 64], hz);

            float a[NHn];
#pragma unroll
            for (int h = 0; h < NHn; h++) {
                __half2 acch = __hmul2(r0, u2h(greg[h][0]));
                acch = __hfma2(r1, u2h(greg[h][1]), acch);
                acch = __hfma2(r2, u2h(greg[h][2]), acch);
                float2 f = __half22float2(acch);
                a[h] = f.x + f.y;
            }
            // reduce-scatter over 32 lanes: lane l ends owning head l>>2
            {
                bool hb = lane & 16;
#pragma unroll
                for (int k2 = 0; k2 < 4; k2++) {
                    float send = hb ? a[k2] : a[k2 + 4];
                    float got = __shfl_xor_sync(0xffffffffu, send, 16);
                    a[k2] = (hb ? a[k2 + 4] : a[k2]) + got;
                }
            }
            {
                bool hb = lane & 8;
#pragma unroll
                for (int k2 = 0; k2 < 2; k2++) {
                    float send = hb ? a[k2] : a[k2 + 2];
                    float got = __shfl_xor_sync(0xffffffffu, send, 8);
                    a[k2] = (hb ? a[k2 + 2] : a[k2]) + got;
                }
            }
            {
                bool hb = lane & 4;
                float send = hb ? a[0] : a[1];
                float got = __shfl_xor_sync(0xffffffffu, send, 4);
                a[0] = (hb ? a[1] : a[0]) + got;
            }
            a[0] += __shfl_xor_sync(0xffffffffu, a[0], 2);
            a[0] += __shfl_xor_sync(0xffffffffu, a[0], 1);
            if ((lane & 3) == 0) sc[lane >> 2][j] += a[0];
        }
    }
    __syncthreads();

    // ---- scale + mask
    {
        bool valid = tid < lim;
        const float scale = 0.223606797749979f;  // 1/sqrt(20)
#pragma unroll
        for (int h = 0; h < NHn; h++) {
            float sv = sc[h][tid] * scale;
            sc[h][tid] = valid ? sv : -1e15f;
        }
    }
    __syncthreads();

    // ---- per-head softmax (warp w = head w); unnormalized p + 1/sum
    {
        int h = w;
        float m = -1e30f;
#pragma unroll
        for (int q = 0; q < 8; q++) m = fmaxf(m, sc[h][lane + q * 32]);
#pragma unroll
        for (int off = 16; off; off >>= 1) m = fmaxf(m, __shfl_xor_sync(0xffffffffu, m, off));
        float ssum = 0.f;
#pragma unroll
        for (int q = 0; q < 8; q++) {
            float p = __expf(sc[h][lane + q * 32] - m);
            sc[h][lane + q * 32] = p;
            ssum += p;
        }
#pragma unroll
        for (int off = 16; off; off >>= 1) ssum += __shfl_xor_sync(0xffffffffu, ssum, off);
        if (lane == 0) rinv[h] = 1.0f / ssum;
    }
    __syncthreads();

    // ---- out[c] = (sum_j p[h][j] * V[b,j,c]) * rinv[h]
    if (tid < Hn) {
        int c = tid;
        int h = c / HDn;
        const float* vp = dV + (size_t)b * Sn * Hn + c;
        float acc = 0.f;
#pragma unroll 16
        for (int j = 0; j < Sn; j++) acc += sc[h][j] * vp[(size_t)j * Hn];
        dATT[((size_t)b * Sn + i) * Hn + c] = acc * rinv[h];
    }
}

// ------------------------- K4: @W_fin + b_fin, x2, LN1 (R2=8, MLP16) --------
__global__ void k_fin_ln(const float* __restrict__ W_fin, const float* __restrict__ b_fin,
                         const float* __restrict__ g1, const float* __restrict__ be1) {
    int row0 = blockIdx.x * R2;
    int c = threadIdx.x;
    int lane = c & 31, w = c >> 5;
    __shared__ float xs[R2][Hn];
    __shared__ float ys[R2][Hn];
    __shared__ float part1[5], part2[5];
    __shared__ float mu_s, rs_s;
#pragma unroll
    for (int r = 0; r < R2; r++) xs[r][c] = dATT[(row0 + r) * Hn + c];
    __syncthreads();
    float acc[R2];
#pragma unroll
    for (int r = 0; r < R2; r++) acc[r] = b_fin[c];
    {
        const float* wp = W_fin + c;
        for (int k0 = 0; k0 < Hn; k0 += 16) {
            float wb[16];
#pragma unroll
            for (int q = 0; q < 16; q++) wb[q] = wp[(k0 + q) * Hn];
#pragma unroll
            for (int q = 0; q < 16; q++)
#pragma unroll
                for (int r = 0; r < R2; r++) acc[r] += xs[r][k0 + q] * wb[q];
        }
    }
#pragma unroll
    for (int r = 0; r < R2; r++) ys[r][c] = 2.f * acc[r];
    __syncthreads();
    for (int r = 0; r < R2; r++) {
        float v = ys[r][c];
        float s1 = v, s2 = v * v;
#pragma unroll
        for (int off = 16; off; off >>= 1) {
            s1 += __shfl_xor_sync(0xffffffffu, s1, off);
            s2 += __shfl_xor_sync(0xffffffffu, s2, off);
        }
        if (lane == 0) { part1[w] = s1; part2[w] = s2; }
        __syncthreads();
        if (c == 0) {
            float a = 0.f, q = 0.f;
#pragma unroll
            for (int t = 0; t < 5; t++) { a += part1[t]; q += part2[t]; }
            float mu = a / Hn;
            mu_s = mu;
            rs_s = rsqrtf(q / Hn - mu * mu + 1e-5f);
        }
        __syncthreads();
        dY1[(row0 + r) * Hn + c] = (v - mu_s) * rs_s * g1[c] + be1[c];
        __syncthreads();
    }
}

// ------------------------- K5: FFN1 = relu(y1 @ W1 + b1), 16-row x col-half --
#define RF1 16
__global__ void k_ffn1(const float* __restrict__ W1, const float* __restrict__ b1) {
    int rb = blockIdx.x >> 1;
    int half = blockIdx.x & 1;
    int row0 = rb * RF1;
    int t = threadIdx.x;  // 320
    int c = half * 320 + t;
    __shared__ float xs[RF1 * Hn];
    for (int q = t; q < RF1 * Hn; q += 320) xs[q] = dY1[row0 * Hn + q];
    __syncthreads();
    float a0[RF1];
#pragma unroll
    for (int r = 0; r < RF1; r++) a0[r] = b1[c];
    {
        const float* wp = W1 + c;
        for (int k0 = 0; k0 < Hn; k0 += 16) {
            float wb[16];
#pragma unroll
            for (int q = 0; q < 16; q++) wb[q] = wp[(k0 + q) * FFn];
#pragma unroll
            for (int q = 0; q < 16; q++)
#pragma unroll
                for (int r = 0; r < RF1; r++) a0[r] += xs[r * Hn + k0 + q] * wb[q];
        }
    }
#pragma unroll
    for (int r = 0; r < RF1; r++) dH1[(row0 + r) * FFn + c] = fmaxf(a0[r], 0.f);
}

// ------------------------- K6: FFN2 + b2, x2, LN2 -> out (split-k x2) -------
__global__ void k_ffn2_ln(const float* __restrict__ W2, const float* __restrict__ b2,
                          const float* __restrict__ g2, const float* __restrict__ be2,
                          float* __restrict__ out) {
    int row0 = blockIdx.x * R2;
    int tid = threadIdx.x;  // 320
    int kh = (tid >= Hn) ? 1 : 0;
    int c = tid - kh * Hn;
    int lane = tid & 31, w = tid >> 5;
    __shared__ float hs[R2 * FFn];
    __shared__ float psum[R2][Hn];
    __shared__ float ys[R2][Hn];
    __shared__ float part1[5], part2[5];
    __shared__ float mu_s, rs_s;
    for (int q = tid; q < R2 * FFn; q += 320) hs[q] = dH1[row0 * FFn + q];
    __syncthreads();
    float acc[R2];
#pragma unroll
    for (int r = 0; r < R2; r++) acc[r] = kh ? 0.f : b2[c];
    int kbase = kh * 320;
    {
        const float* wp = W2 + (size_t)kbase * Hn + c;
        for (int k0 = 0; k0 < 320; k0 += 16) {
            float wb[16];
#pragma unroll
            for (int q = 0; q < 16; q++) wb[q] = wp[(k0 + q) * Hn];
#pragma unroll
            for (int q = 0; q < 16; q++)
#pragma unroll
                for (int r = 0; r < R2; r++) acc[r] += hs[r * FFn + kbase + k0 + q] * wb[q];
        }
    }
    if (kh) {
#pragma unroll
        for (int r = 0; r < R2; r++) psum[r][c] = acc[r];
    }
    __syncthreads();
    if (!kh) {
#pragma unroll
        for (int r = 0; r < R2; r++) ys[r][c] = 2.f * (acc[r] + psum[r][c]);
    }
    __syncthreads();
    for (int r = 0; r < R2; r++) {
        float v = (tid < Hn) ? ys[r][c] : 0.f;
        float s1 = v, s2 = v * v;
#pragma unroll
        for (int off = 16; off; off >>= 1) {
            s1 += __shfl_xor_sync(0xffffffffu, s1, off);
            s2 += __shfl_xor_sync(0xffffffffu, s2, off);
        }
        if (lane == 0 && w < 5) { part1[w] = s1; part2[w] = s2; }
        __syncthreads();
        if (tid == 0) {
            float a = 0.f, q = 0.f;
#pragma unroll
            for (int t = 0; t < 5; t++) { a += part1[t]; q += part2[t]; }
            float mu = a / Hn;
            mu_s = mu;
            rs_s = rsqrtf(q / Hn - mu * mu + 1e-5f);
        }
        __syncthreads();
        if (tid < Hn) out[(row0 + r) * Hn + c] = (ys[r][c] - mu_s) * rs_s * g2[c] + be2[c];
        __syncthreads();
    }
}

// ------------------------- launch -------------------------------------------
extern "C" void kernel_launch(void* const* d_in, const int* in_sizes, int n_in,
                              void* d_out, int out_size) {
    const float* inp   = (const float*)d_in[0];
    const int* pos_s   = (const int*)d_in[1];
    const int* pos_e   = (const int*)d_in[2];
    const int* seq_len = (const int*)d_in[3];
    const int* lex     = (const int*)d_in[4];
    const float* pe_ss = (const float*)d_in[5];
    const float* pe_se = (const float*)d_in[6];
    const float* pe_es = (const float*)d_in[7];
    const float* pe_ee = (const float*)d_in[8];
    const float* W_fus = (const float*)d_in[9];
    const float* b_fus = (const float*)d_in[10];
    const float* Wq    = (const float*)d_in[11];
    const float* bq    = (const float*)d_in[12];
    const float* Wk    = (const float*)d_in[13];
    const float* bk    = (const float*)d_in[14];
    const float* Wv    = (const float*)d_in[15];
    const float* bv    = (const float*)d_in[16];
    const float* Wr    = (const float*)d_in[17];
    // d_in[18] = br: constant over j inside softmax -> cancels exactly, unused
    const float* u     = (const float*)d_in[19];
    const float* v     = (const float*)d_in[20];
    const float* W_fin = (const float*)d_in[21];
    const float* b_fin = (const float*)d_in[22];
    const float* ln1_g = (const float*)d_in[23];
    const float* ln1_b = (const float*)d_in[24];
    const float* W1    = (const float*)d_in[25];
    const float* b1    = (const float*)d_in[26];
    const float* W2    = (const float*)d_in[27];
    const float* b2    = (const float*)d_in[28];
    const float* ln2_g = (const float*)d_in[29];
    const float* ln2_b = (const float*)d_in[30];

    k_tables<<<2 * TBLOCKS, Hn>>>(pe_ss, pe_se, W_fus, b_fus, 0);     // 1
    k_tables<<<2 * TBLOCKS, Hn>>>(pe_es, pe_ee, W_fus, b_fus, 2);     // 2
    k_qkvg<<<BSn / R2, Hn>>>(inp, Wq, bq, Wk, bk, Wv, bv, Wr, u, v);  // 3
    k_attn<<<BSn, 256>>>(pos_s, pos_e, seq_len, lex);                 // 4 (profiled)
    k_fin_ln<<<BSn / R2, Hn>>>(W_fin, b_fin, ln1_g, ln1_b);           // 5
    k_ffn1<<<(BSn / RF1) * 2, 320>>>(W1, b1);                         // 6
    k_ffn2_ln<<<BSn / R2, 320>>>(W2, b2, ln2_g, ln2_b, (float*)d_out);// 7
}